// round 5
// baseline (speedup 1.0000x reference)
#include <cuda_runtime.h>
#include <cuda_fp16.h>
#include <cstdint>

#define BB 16
#define TT 1024
#define HH 256
#define LL 2048
#define MQ 64
#define TCHK 64
#define NCHUNK (TT / TCHK)

// smem pitches (halves). Pitch % 64 must be in {8,24,40,56} for conflict-free ldsm.
#define QP 264
#define XP 264
#define ECP 72

// smem byte offsets (all 16B aligned)
#define SO_RS4  0                        // float rs4[4][64]
#define SO_INV  1024                     // float inv[64]
#define SO_FLAG 1536
#define SO_Q    2048                     // 64*264*2 = 33792
#define SO_X0   (2048 + 33792)           // 35840
#define SO_X1   (SO_X0 + 33792)          // 69632
#define SO_EC   (SO_X1 + 33792)          // 103424: 64*72*2 = 9216
#define SMEM_BYTES (SO_EC + 9216)        // 112640 (110 KB) -> 2 CTAs/SM

// fp16 copy of X, filled by convert kernel
__device__ __half g_Xh[(size_t)BB * TT * HH];

__device__ __forceinline__ uint32_t smem_u32(const void* p) {
    uint32_t a;
    asm("{ .reg .u64 t; cvta.to.shared.u64 t, %1; cvt.u32.u64 %0, t; }" : "=r"(a) : "l"(p));
    return a;
}
__device__ __forceinline__ void ldsm4(uint32_t a, uint32_t* r) {
    asm volatile("ldmatrix.sync.aligned.m8n8.x4.shared.b16 {%0,%1,%2,%3}, [%4];"
                 : "=r"(r[0]), "=r"(r[1]), "=r"(r[2]), "=r"(r[3]) : "r"(a));
}
__device__ __forceinline__ void ldsm4t(uint32_t a, uint32_t* r) {
    asm volatile("ldmatrix.sync.aligned.m8n8.x4.trans.shared.b16 {%0,%1,%2,%3}, [%4];"
                 : "=r"(r[0]), "=r"(r[1]), "=r"(r[2]), "=r"(r[3]) : "r"(a));
}
__device__ __forceinline__ void mma16816(float* d, const uint32_t* a, const uint32_t* b) {
    asm volatile("mma.sync.aligned.m16n8k16.row.col.f32.f16.f16.f32 "
                 "{%0,%1,%2,%3}, {%4,%5,%6,%7}, {%8,%9}, {%0,%1,%2,%3};"
                 : "+f"(d[0]), "+f"(d[1]), "+f"(d[2]), "+f"(d[3])
                 : "r"(a[0]), "r"(a[1]), "r"(a[2]), "r"(a[3]), "r"(b[0]), "r"(b[1]));
}
__device__ __forceinline__ void cpasync16(uint32_t sa, const void* ga) {
    asm volatile("cp.async.ca.shared.global [%0], [%1], 16;" :: "r"(sa), "l"(ga));
}
#define CP_COMMIT()  asm volatile("cp.async.commit_group;" ::: "memory")
#define CP_WAIT(n)   asm volatile("cp.async.wait_group %0;" :: "n"(n) : "memory")

// ---------------- X f32 -> fp16 convert kernel ----------------
__global__ void __launch_bounds__(256)
xconv(const float* __restrict__ X)
{
    const size_t i = ((size_t)blockIdx.x * 256 + threadIdx.x) * 8;
    float4 a = *(const float4*)(X + i);
    float4 b = *(const float4*)(X + i + 4);
    half2 h[4] = { __floats2half2_rn(a.x, a.y), __floats2half2_rn(a.z, a.w),
                   __floats2half2_rn(b.x, b.y), __floats2half2_rn(b.z, b.w) };
    *(uint4*)(g_Xh + i) = *(uint4*)h;
}

// ---------------- main fused kernel ----------------
__global__ void __launch_bounds__(256, 2)
pla_mma(const void*  __restrict__ labels_raw, // (B,L) int32/int64
        const float* __restrict__ table,      // (C+1,H)
        float* __restrict__ logits,           // (B,L,H)
        float* __restrict__ att)              // (B,L,T)
{
    extern __shared__ char sm[];
    float*  rs4 = (float*)(sm + SO_RS4);
    float*  inv = (float*)(sm + SO_INV);
    __half* Qs  = (__half*)(sm + SO_Q);
    __half* Ec  = (__half*)(sm + SO_EC);
    const uint32_t smb = smem_u32(sm);
    const uint32_t Qb = smb + SO_Q, Xb0 = smb + SO_X0, Eb = smb + SO_EC;

    const int tid = threadIdx.x, lane = tid & 31, w = tid >> 5;
    const int wm = w & 1, wn = w >> 1;       // warp grid: 2(M) x 4(N)
    const int m0 = wm * 32;
    const int b = blockIdx.x >> 5, lt = blockIdx.x & 31, l0 = lt * MQ;
    const size_t bL = (size_t)b * LL;
    const __half* Xg = g_Xh + (size_t)b * TT * HH;

    rs4[tid] = 0.f;

    // cp.async issue helper geometry: 4 threads per t-row, 8x16B each
    const int xr = tid >> 2, xc = (tid & 3) * 64;   // row 0..63, col halves
    const uint32_t xdst_row = (uint32_t)(xr * XP + xc) * 2;

    // ---- issue chunk 0 ----
    {
        const __half* src = Xg + (size_t)xr * HH + xc;
        #pragma unroll
        for (int j = 0; j < 8; j++)
            cpasync16(Xb0 + xdst_row + j * 16, src + j * 8);
        CP_COMMIT();
    }

    // labels dtype detection (int64 LE, values < 2^31 => odd words zero)
    int* flag = (int*)(sm + SO_FLAG);
    if (tid == 0) {
        const int* li = (const int*)labels_raw;
        *flag = ((li[1] | li[3] | li[5] | li[7] | li[9] | li[11] | li[13] | li[15]) == 0);
    }
    __syncthreads();
    const bool is64 = (*flag != 0);

    // ---- gather Q (table[labels]) -> fp16 smem (overlaps chunk-0 load) ----
    {
        const int q = tid >> 2, c0 = (tid & 3) * 4;
        const long long lidx = (long long)b * LL + l0 + q;
        const long long lab = is64 ? ((const long long*)labels_raw)[lidx]
                                   : (long long)((const int*)labels_raw)[lidx];
        const float* row = table + (size_t)lab * HH;
        #pragma unroll
        for (int j = 0; j < 16; j++) {
            const int col = c0 + j * 16;
            float4 v = *(const float4*)(row + col);
            *(half2*)(Qs + q * QP + col)     = __floats2half2_rn(v.x, v.y);
            *(half2*)(Qs + q * QP + col + 2) = __floats2half2_rn(v.z, v.w);
        }
    }

    float rsum[4] = {0.f, 0.f, 0.f, 0.f};
    float o[64];
    #pragma unroll
    for (int i = 0; i < 64; i++) o[i] = 0.f;

    const uint32_t a1_0 = Qb + (uint32_t)(((m0 + (lane & 15)) * QP + ((lane >> 4) << 3)) * 2);
    const uint32_t b1r  = (uint32_t)(((wn * 16 + (lane & 7) + ((lane >> 4) << 3)) * XP
                                      + ((lane >> 3) & 1) * 8) * 2);
    const uint32_t a2_0 = Eb + (uint32_t)(((m0 + (lane & 15)) * ECP + ((lane >> 4) << 3)) * 2);
    const uint32_t b2r  = (uint32_t)(((lane & 15) * XP + wn * 64 + ((lane >> 4) << 3)) * 2);

    const int r = lane >> 2, c2 = (lane & 3) * 2;

    for (int tc = 0; tc < NCHUNK; tc++) {
        const uint32_t xcur = Xb0 + (uint32_t)(tc & 1) * 33792u;

        // issue next chunk into other buffer, then wait for current
        if (tc + 1 < NCHUNK) {
            const uint32_t xnxt = Xb0 + (uint32_t)((tc + 1) & 1) * 33792u;
            const __half* src = Xg + (size_t)(tc + 1) * TCHK * HH + (size_t)xr * HH + xc;
            #pragma unroll
            for (int j = 0; j < 8; j++)
                cpasync16(xnxt + xdst_row + j * 16, src + j * 8);
            CP_COMMIT();
            CP_WAIT(1);
        } else {
            CP_WAIT(0);
        }
        __syncthreads();

        // ---- MMA1: S[64x64] = Q * Xchunk^T (K = 256) ----
        float sa[4][4];
        #pragma unroll
        for (int i = 0; i < 4; i++)
            for (int j = 0; j < 4; j++) sa[i][j] = 0.f;
        #pragma unroll 4
        for (int k = 0; k < 16; k++) {
            uint32_t A0[4], A1[4], Bv[4];
            ldsm4(a1_0 + k * 32, A0);
            ldsm4(a1_0 + 16 * QP * 2 + k * 32, A1);
            ldsm4(xcur + b1r + k * 32, Bv);
            mma16816(sa[0], A0, Bv);
            mma16816(sa[1], A0, Bv + 2);
            mma16816(sa[2], A1, Bv);
            mma16816(sa[3], A1, Bv + 2);
        }

        // ---- epilogue: e = exp(s) -> Ec fp16 + running row sums ----
        #pragma unroll
        for (int mf = 0; mf < 2; mf++) {
            #pragma unroll
            for (int nf = 0; nf < 2; nf++) {
                float* s = sa[mf * 2 + nf];
                const float e0 = __expf(s[0]), e1 = __expf(s[1]);
                const float e2 = __expf(s[2]), e3 = __expf(s[3]);
                rsum[mf * 2 + 0] += e0 + e1;
                rsum[mf * 2 + 1] += e2 + e3;
                const int row0 = m0 + mf * 16 + r;
                const int col = wn * 16 + nf * 8 + c2;
                *(half2*)(Ec + row0 * ECP + col)       = __floats2half2_rn(e0, e1);
                *(half2*)(Ec + (row0 + 8) * ECP + col) = __floats2half2_rn(e2, e3);
            }
        }
        __syncthreads();   // Ec visible

        // ---- write unnormalized E chunk to att gmem (coalesced) ----
        {
            const int er = tid >> 2, cb = (tid & 3) * 16;
            float* gd = att + (bL + l0 + er) * TT + tc * TCHK + cb;
            const __half* es = Ec + er * ECP + cb;
            #pragma unroll
            for (int j = 0; j < 4; j++) {
                float2 f0 = __half22float2(*(const half2*)(es + j * 4));
                float2 f1 = __half22float2(*(const half2*)(es + j * 4 + 2));
                *(float4*)(gd + j * 4) = make_float4(f0.x, f0.y, f1.x, f1.y);
            }
        }

        // ---- MMA2: O[64x256] += E_chunk[64x64] * Xchunk[64x256] ----
        #pragma unroll
        for (int kst = 0; kst < 4; kst++) {
            uint32_t A0[4], A1[4], Bv[4][4];
            ldsm4(a2_0 + kst * 32, A0);
            ldsm4(a2_0 + 16 * ECP * 2 + kst * 32, A1);
            #pragma unroll
            for (int nb = 0; nb < 4; nb++)
                ldsm4t(xcur + b2r + kst * 16 * XP * 2 + nb * 32, Bv[nb]);
            #pragma unroll
            for (int nf = 0; nf < 8; nf++) {
                const uint32_t* bp = &Bv[nf >> 1][(nf & 1) * 2];
                mma16816(&o[nf * 4],      A0, bp);
                mma16816(&o[32 + nf * 4], A1, bp);
            }
        }
        __syncthreads();   // Ec + Xs[cur] free
    }

    // ---- reduce row sums, compute inverses ----
    #pragma unroll
    for (int mf = 0; mf < 2; mf++) {
        #pragma unroll
        for (int h = 0; h < 2; h++) {
            float v = rsum[mf * 2 + h];
            v += __shfl_xor_sync(0xffffffffu, v, 1);
            v += __shfl_xor_sync(0xffffffffu, v, 2);
            if ((lane & 3) == 0)
                rs4[wn * 64 + m0 + mf * 16 + h * 8 + r] = v;
        }
    }
    __syncthreads();
    if (tid < 64)
        inv[tid] = 1.0f / (rs4[tid] + rs4[64 + tid] + rs4[128 + tid] + rs4[192 + tid]);
    __syncthreads();

    // ---- write logits (scaled O fragments) ----
    #pragma unroll
    for (int mf = 0; mf < 2; mf++) {
        #pragma unroll
        for (int nf = 0; nf < 8; nf++) {
            const float* ov = &o[mf * 32 + nf * 4];
            const int r0 = m0 + mf * 16 + r;
            const int col = wn * 64 + nf * 8 + c2;
            const float i0 = inv[r0], i1 = inv[r0 + 8];
            float* d0 = logits + (bL + l0 + r0) * HH + col;
            float* d1 = logits + (bL + l0 + r0 + 8) * HH + col;
            *(float2*)d0 = make_float2(ov[0] * i0, ov[1] * i0);
            *(float2*)d1 = make_float2(ov[2] * i1, ov[3] * i1);
        }
    }

    // ---- normalize att in-place (mostly L2-resident RMW) ----
    {
        float4* Ab = (float4*)(att + (bL + l0) * TT);
        #pragma unroll 4
        for (int i = tid; i < MQ * TT / 4; i += 256) {
            float4 v = Ab[i];
            const float iv = inv[i >> 8];  // 256 float4 per row
            v.x *= iv; v.y *= iv; v.z *= iv; v.w *= iv;
            Ab[i] = v;
        }
    }
}

extern "C" void kernel_launch(void* const* d_in, const int* in_sizes, int n_in,
                              void* d_out, int out_size)
{
    const float* X      = (const float*)d_in[0];
    const void*  labels = d_in[1];
    const float* table  = (const float*)d_in[2];
    float* logits = (float*)d_out;
    float* att    = logits + (size_t)BB * LL * HH;

    xconv<<<(BB * TT * HH) / (256 * 8), 256>>>(X);

    cudaFuncSetAttribute(pla_mma, cudaFuncAttributeMaxDynamicSharedMemorySize, SMEM_BYTES);
    pla_mma<<<BB * (LL / MQ), 256, SMEM_BYTES>>>(labels, table, logits, att);
}

// round 6
// speedup vs baseline: 1.0428x; 1.0428x over previous
#include <cuda_runtime.h>
#include <cuda_fp16.h>
#include <cstdint>

#define BB 16
#define TT 1024
#define HH 256
#define LL 2048
#define MQ 64
#define TCHK 64
#define NCHUNK (TT / TCHK)
#define NTHR 512

// smem pitches (halves); byte stride = odd multiple of 16B -> conflict-free ldsm
#define QP 264
#define XP 264
#define ECP 72
#define XCHB (TCHK * XP * 2)     // 33792 bytes per X buffer

// smem byte offsets
#define SO_RS4  0                        // float rs4[4][64]
#define SO_INV  1024                     // float inv[64]
#define SO_FLAG 1536
#define SO_Q    2048                     // 64*264*2 = 33792
#define SO_X0   (SO_Q + 33792)
#define SO_EC   (SO_X0 + 2 * XCHB)      // 64*72*2 = 9216
#define SMEM_BYTES (SO_EC + 9216)       // 112640 B

__device__ __half g_Xh[(size_t)BB * TT * HH];

__device__ __forceinline__ uint32_t smem_u32(const void* p) {
    uint32_t a;
    asm("{ .reg .u64 t; cvta.to.shared.u64 t, %1; cvt.u32.u64 %0, t; }" : "=r"(a) : "l"(p));
    return a;
}
__device__ __forceinline__ void ldsm4(uint32_t a, uint32_t* r) {
    asm volatile("ldmatrix.sync.aligned.m8n8.x4.shared.b16 {%0,%1,%2,%3}, [%4];"
                 : "=r"(r[0]), "=r"(r[1]), "=r"(r[2]), "=r"(r[3]) : "r"(a));
}
__device__ __forceinline__ void ldsm4t(uint32_t a, uint32_t* r) {
    asm volatile("ldmatrix.sync.aligned.m8n8.x4.trans.shared.b16 {%0,%1,%2,%3}, [%4];"
                 : "=r"(r[0]), "=r"(r[1]), "=r"(r[2]), "=r"(r[3]) : "r"(a));
}
__device__ __forceinline__ void mma16816(float* d, const uint32_t* a, const uint32_t* b) {
    asm volatile("mma.sync.aligned.m16n8k16.row.col.f32.f16.f16.f32 "
                 "{%0,%1,%2,%3}, {%4,%5,%6,%7}, {%8,%9}, {%0,%1,%2,%3};"
                 : "+f"(d[0]), "+f"(d[1]), "+f"(d[2]), "+f"(d[3])
                 : "r"(a[0]), "r"(a[1]), "r"(a[2]), "r"(a[3]), "r"(b[0]), "r"(b[1]));
}
__device__ __forceinline__ void cpasync16(uint32_t sa, const void* ga) {
    asm volatile("cp.async.ca.shared.global [%0], [%1], 16;" :: "r"(sa), "l"(ga));
}
#define CP_COMMIT()  asm volatile("cp.async.commit_group;" ::: "memory")
#define CP_WAIT(n)   asm volatile("cp.async.wait_group %0;" :: "n"(n) : "memory")

// ---------------- X f32 -> fp16 convert ----------------
__global__ void __launch_bounds__(256)
xconv(const float* __restrict__ X)
{
    const size_t i = ((size_t)blockIdx.x * 256 + threadIdx.x) * 8;
    float4 a = *(const float4*)(X + i);
    float4 b = *(const float4*)(X + i + 4);
    half2 h[4] = { __floats2half2_rn(a.x, a.y), __floats2half2_rn(a.z, a.w),
                   __floats2half2_rn(b.x, b.y), __floats2half2_rn(b.z, b.w) };
    *(uint4*)(g_Xh + i) = *(uint4*)h;
}

// ---------------- main fused kernel: 512 threads, 4M x 4N warps ----------------
__global__ void __launch_bounds__(NTHR, 1)
pla_mma(const void*  __restrict__ labels_raw, // (B,L) int32/int64
        const float* __restrict__ table,      // (C+1,H)
        float* __restrict__ logits,           // (B,L,H)
        float* __restrict__ att)              // (B,L,T)
{
    extern __shared__ char sm[];
    float*  rs4 = (float*)(sm + SO_RS4);
    float*  inv = (float*)(sm + SO_INV);
    __half* Qs  = (__half*)(sm + SO_Q);
    __half* Ec  = (__half*)(sm + SO_EC);
    const uint32_t smb = smem_u32(sm);
    const uint32_t Qb = smb + SO_Q, Xb0 = smb + SO_X0, Eb = smb + SO_EC;

    const int tid = threadIdx.x, lane = tid & 31, w = tid >> 5;
    const int wm = w & 3, wn = w >> 2;       // 4(M) x 4(N)
    const int m0 = wm * 16;
    const int b = blockIdx.x >> 5, lt = blockIdx.x & 31, l0 = lt * MQ;
    const size_t bL = (size_t)b * LL;
    const __half* Xg = g_Xh + (size_t)b * TT * HH;

    if (tid < 256) rs4[tid] = 0.f;

    // cp.async geometry: 8 threads per t-row, 4 x 16B each
    const int xr = tid >> 3, xc = (tid & 7) * 32;   // row 0..63, col in halves
    const uint32_t xdst_row = (uint32_t)(xr * XP + xc) * 2;

    // ---- issue chunk 0 ----
    {
        const __half* src = Xg + (size_t)xr * HH + xc;
        #pragma unroll
        for (int j = 0; j < 4; j++)
            cpasync16(Xb0 + xdst_row + j * 16, src + j * 8);
        CP_COMMIT();
    }

    // labels dtype detection (int64 LE, values < 2^31 => odd words zero)
    int* flag = (int*)(sm + SO_FLAG);
    if (tid == 0) {
        const int* li = (const int*)labels_raw;
        *flag = ((li[1] | li[3] | li[5] | li[7] | li[9] | li[11] | li[13] | li[15]) == 0);
    }
    __syncthreads();
    const bool is64 = (*flag != 0);

    // ---- gather Q (table[labels]) -> fp16 smem ----
    {
        const int q = tid >> 3, c0 = (tid & 7) * 4;
        const long long lidx = (long long)b * LL + l0 + q;
        const long long lab = is64 ? ((const long long*)labels_raw)[lidx]
                                   : (long long)((const int*)labels_raw)[lidx];
        const float* row = table + (size_t)lab * HH;
        #pragma unroll
        for (int j = 0; j < 8; j++) {
            const int col = c0 + j * 32;
            float4 v = *(const float4*)(row + col);
            *(half2*)(Qs + q * QP + col)     = __floats2half2_rn(v.x, v.y);
            *(half2*)(Qs + q * QP + col + 2) = __floats2half2_rn(v.z, v.w);
        }
    }

    float rsum0 = 0.f, rsum1 = 0.f;   // rows m0+r, m0+8+r
    float o[32];
    #pragma unroll
    for (int i = 0; i < 32; i++) o[i] = 0.f;

    const uint32_t a1_0 = Qb + (uint32_t)(((m0 + (lane & 15)) * QP + ((lane >> 4) << 3)) * 2);
    const uint32_t b1r  = (uint32_t)(((wn * 16 + (lane & 7) + ((lane >> 4) << 3)) * XP
                                      + ((lane >> 3) & 1) * 8) * 2);
    const uint32_t a2_0 = Eb + (uint32_t)(((m0 + (lane & 15)) * ECP + ((lane >> 4) << 3)) * 2);
    const uint32_t b2r  = (uint32_t)(((lane & 15) * XP + wn * 64 + ((lane >> 4) << 3)) * 2);

    const int r = lane >> 2, c2 = (lane & 3) * 2;

    for (int tc = 0; tc < NCHUNK; tc++) {
        const uint32_t xcur = Xb0 + (uint32_t)(tc & 1) * XCHB;

        if (tc + 1 < NCHUNK) {
            const uint32_t xnxt = Xb0 + (uint32_t)((tc + 1) & 1) * XCHB;
            const __half* src = Xg + (size_t)(tc + 1) * TCHK * HH + (size_t)xr * HH + xc;
            #pragma unroll
            for (int j = 0; j < 4; j++)
                cpasync16(xnxt + xdst_row + j * 16, src + j * 8);
            CP_COMMIT();
            CP_WAIT(1);
        } else {
            CP_WAIT(0);
        }
        __syncthreads();

        // ---- MMA1: S[16 x 16 per warp] = Q * Xchunk^T (K = 256) ----
        float sa[4][4];
        #pragma unroll
        for (int i = 0; i < 4; i++)
            for (int j = 0; j < 4; j++) sa[i][j] = 0.f;
        #pragma unroll 4
        for (int k = 0; k < 16; k++) {
            uint32_t A0[4], Bv[4];
            ldsm4(a1_0 + k * 32, A0);
            ldsm4(xcur + b1r + k * 32, Bv);
            mma16816(sa[0], A0, Bv);
            mma16816(sa[1], A0, Bv + 2);
        }
        // sa[2], sa[3] unused in MMA1 (kept for uniform epilogue shape below)

        // ---- epilogue: e = exp(s) -> Ec fp16 + running row sums ----
        #pragma unroll
        for (int nf = 0; nf < 2; nf++) {
            float* s = sa[nf];
            const float e0 = __expf(s[0]), e1 = __expf(s[1]);
            const float e2 = __expf(s[2]), e3 = __expf(s[3]);
            rsum0 += e0 + e1;
            rsum1 += e2 + e3;
            const int row0 = m0 + r;
            const int col = wn * 16 + nf * 8 + c2;
            *(half2*)(Ec + row0 * ECP + col)       = __floats2half2_rn(e0, e1);
            *(half2*)(Ec + (row0 + 8) * ECP + col) = __floats2half2_rn(e2, e3);
        }
        __syncthreads();   // Ec visible to all warps

        // ---- write unnormalized E chunk to att gmem (coalesced) ----
        {
            const int er = tid >> 3, cb = (tid & 7) * 8;
            float* gd = att + (bL + l0 + er) * TT + tc * TCHK + cb;
            const __half* es = Ec + er * ECP + cb;
            #pragma unroll
            for (int j = 0; j < 2; j++) {
                float2 f0 = __half22float2(*(const half2*)(es + j * 4));
                float2 f1 = __half22float2(*(const half2*)(es + j * 4 + 2));
                *(float4*)(gd + j * 4) = make_float4(f0.x, f0.y, f1.x, f1.y);
            }
        }

        // ---- MMA2: O[16 x 64 per warp] += E[16 x 64] * Xchunk[64 x 64-slice] ----
        #pragma unroll
        for (int kst = 0; kst < 4; kst++) {
            uint32_t A0[4], Bv[4][4];
            ldsm4(a2_0 + kst * 32, A0);
            #pragma unroll
            for (int nb = 0; nb < 4; nb++)
                ldsm4t(xcur + b2r + kst * 16 * XP * 2 + nb * 32, Bv[nb]);
            #pragma unroll
            for (int nf = 0; nf < 8; nf++)
                mma16816(&o[nf * 4], A0, &Bv[nf >> 1][(nf & 1) * 2]);
        }
        __syncthreads();   // Ec + Xs[cur] free
    }

    // ---- reduce row sums across quad lanes, publish, compute inverses ----
    {
        float v0 = rsum0, v1 = rsum1;
        v0 += __shfl_xor_sync(0xffffffffu, v0, 1);
        v0 += __shfl_xor_sync(0xffffffffu, v0, 2);
        v1 += __shfl_xor_sync(0xffffffffu, v1, 1);
        v1 += __shfl_xor_sync(0xffffffffu, v1, 2);
        if ((lane & 3) == 0) {
            rs4[wn * 64 + m0 + r]     = v0;
            rs4[wn * 64 + m0 + 8 + r] = v1;
        }
    }
    __syncthreads();
    if (tid < 64)
        inv[tid] = 1.0f / (rs4[tid] + rs4[64 + tid] + rs4[128 + tid] + rs4[192 + tid]);
    __syncthreads();

    // ---- write logits (scaled O fragments) ----
    {
        const int r0 = m0 + r;
        const float i0 = inv[r0], i1 = inv[r0 + 8];
        float* d0 = logits + (bL + l0 + r0) * HH;
        float* d1 = logits + (bL + l0 + r0 + 8) * HH;
        #pragma unroll
        for (int nf = 0; nf < 8; nf++) {
            const float* ov = &o[nf * 4];
            const int col = wn * 64 + nf * 8 + c2;
            *(float2*)(d0 + col) = make_float2(ov[0] * i0, ov[1] * i0);
            *(float2*)(d1 + col) = make_float2(ov[2] * i1, ov[3] * i1);
        }
    }

    // ---- normalize att in-place (mostly L2-resident RMW) ----
    {
        float4* Ab = (float4*)(att + (bL + l0) * TT);
        #pragma unroll 4
        for (int i = tid; i < MQ * TT / 4; i += NTHR) {
            float4 v = Ab[i];
            const float iv = inv[i >> 8];  // 256 float4 per row
            v.x *= iv; v.y *= iv; v.z *= iv; v.w *= iv;
            Ab[i] = v;
        }
    }
}

extern "C" void kernel_launch(void* const* d_in, const int* in_sizes, int n_in,
                              void* d_out, int out_size)
{
    const float* X      = (const float*)d_in[0];
    const void*  labels = d_in[1];
    const float* table  = (const float*)d_in[2];
    float* logits = (float*)d_out;
    float* att    = logits + (size_t)BB * LL * HH;

    xconv<<<(BB * TT * HH) / (256 * 8), 256>>>(X);

    cudaFuncSetAttribute(pla_mma, cudaFuncAttributeMaxDynamicSharedMemorySize, SMEM_BYTES);
    pla_mma<<<BB * (LL / MQ), NTHR, SMEM_BYTES>>>(labels, table, logits, att);
}